// round 5
// baseline (speedup 1.0000x reference)
#include <cuda_runtime.h>
#include <cstdint>

#define NA     17064
#define KTOP   1000
#define NBINS  16384
#define CCAP   4096
#define NT     1024
#define B      16

typedef unsigned long long u64;

// ---- shared memory arena (byte offsets, phase-aliased) ----
#define OFF_SCORES 0         // float[17064]            (phase 1-3)
#define OFF_HIST   68256     // u32[16384]  end 133792  (phase 1-3)
#define OFF_CIDX   133792    // u32[4096]   end 150176  (phase 3-4)
#define OFF_CAND   0         // u64[4096]   end 32768   (phase 4-6, aliases scores)
#define OFF_MAT    0         // u32[1000*32] end 128000 (phase 7-8, aliases cand)
#define OFF_SX1    128000
#define OFF_SY1    132000
#define OFF_SX2    136000
#define OFF_SY2    140000
#define OFF_AREA   144000
#define OFF_BOX    148000    // float4[1000] end 164000
#define OFF_SCORE  164000
#define OFF_LABEL  168000
#define OFF_VALID  172000    // end 176000
#define SMEM_TOTAL 176000

// Exact sigmoid: float exp via double exp (correctly rounded to float =>
// matches faithful libm expf), then float add + div as XLA expands logistic.
__device__ __forceinline__ float sigx(float x) {
    float t = (float)exp(-(double)x);
    return __fdiv_rn(1.0f, __fadd_rn(1.0f, t));
}
// Fast approximate sigmoid — superset selection only.
__device__ __forceinline__ float siga(float x) {
    return __fdividef(1.0f, 1.0f + __expf(-x));
}
// compare-exchange via shfl (bitonic)
__device__ __forceinline__ u64 cex_shfl(u64 v, int j, bool up, int lane) {
    u64 p = __shfl_xor_sync(0xffffffffu, v, j);
    bool lower = ((lane & j) == 0);
    return (lower == up) ? (v > p ? v : p) : (v < p ? v : p);
}

extern __shared__ unsigned char smem_raw[];

__global__ void __launch_bounds__(NT, 1)
fcos_all(const float* __restrict__ cls, const float* __restrict__ ctr,
         const float* __restrict__ reg, const float* __restrict__ coords,
         const float* __restrict__ pstr, float* __restrict__ out)
{
    const int b    = blockIdx.x;
    const int tid  = threadIdx.x;
    const int lane = tid & 31;
    const int wid  = tid >> 5;

    float*    scores = (float*)(smem_raw + OFF_SCORES);
    unsigned* hist   = (unsigned*)(smem_raw + OFF_HIST);
    unsigned* cidx   = (unsigned*)(smem_raw + OFF_CIDX);
    u64*      cand   = (u64*)(smem_raw + OFF_CAND);
    unsigned* mat    = (unsigned*)(smem_raw + OFF_MAT);
    float*  sx1  = (float*)(smem_raw + OFF_SX1);
    float*  sy1  = (float*)(smem_raw + OFF_SY1);
    float*  sx2  = (float*)(smem_raw + OFF_SX2);
    float*  sy2  = (float*)(smem_raw + OFF_SY2);
    float*  sar  = (float*)(smem_raw + OFF_AREA);
    float4* sbox = (float4*)(smem_raw + OFF_BOX);
    float*  ssc  = (float*)(smem_raw + OFF_SCORE);
    unsigned* slab = (unsigned*)(smem_raw + OFF_LABEL);
    unsigned* sval = (unsigned*)(smem_raw + OFF_VALID);

    __shared__ unsigned chunk[1024];
    __shared__ float redmax[32], redmin[32];
    __shared__ float s_mx, s_mn;
    __shared__ unsigned s_thr, s_cnt, srem[32];

    const float4* clsB = (const float4*)cls + (size_t)b * NA;
    const float*  ctrB = ctr + (size_t)b * NA;

    // ---------------- Phase 1: approx scores + smem histogram ----------------
    for (int i = tid; i < NBINS; i += NT) hist[i] = 0;
    if (tid == 0) s_cnt = 0;
    __syncthreads();

    for (int i = tid; i < NA; i += NT) {
        float4 c = clsB[i];
        float m = fmaxf(fmaxf(c.x, c.y), fmaxf(c.z, c.w));   // sigmoid monotone
        float score = __fsqrt_rn(siga(m) * siga(ctrB[i]));
        scores[i] = score;
        atomicAdd(&hist[__float_as_uint(score) >> 16], 1u);
    }
    __syncthreads();

    // ---------------- Phase 2: threshold (one-bin superset margin) -----------
    { unsigned s = 0; int base = tid * 16;
#pragma unroll
      for (int q = 0; q < 16; ++q) s += hist[base + q];
      chunk[tid] = s; }
    __syncthreads();
    if (tid == 0) {
        unsigned acc = 0; int T = 0;
        for (int c = 1023; c >= 0; --c) {
            unsigned a2 = acc + chunk[c];
            if (a2 >= KTOP) {
                for (int bin = c * 16 + 15; bin >= c * 16; --bin) {
                    acc += hist[bin];
                    if (acc >= KTOP) { T = bin; break; }
                }
                break;
            }
            acc = a2;
        }
        s_thr = (unsigned)(T > 0 ? T - 1 : 0);
    }
    __syncthreads();
    const unsigned T = s_thr;

    // ---------------- Phase 3: compact candidate superset ----------------
    for (int i = tid; i < NA; i += NT) {
        if ((__float_as_uint(scores[i]) >> 16) >= T) {
            unsigned p = atomicAdd(&s_cnt, 1u);
            if (p < CCAP) cidx[p] = (unsigned)i;
        }
    }
    __syncthreads();
    int C = (int)s_cnt; if (C > CCAP) C = CCAP;
    __syncthreads();   // all reads of scores done before cand overwrites

    // ---------------- Phase 4: exact rescore (2 FP64 exps/cand) --------------
    for (int p = tid; p < C; p += NT) {
        unsigned idx = cidx[p];
        float4 c = clsB[idx];
        float xs0 = c.x, xs1 = c.y, xs2 = c.z, xs3 = c.w;
        float m = xs0; int im = 0;
        if (xs1 > m) { m = xs1; im = 1; }
        if (xs2 > m) { m = xs2; im = 2; }
        if (xs3 > m) { m = xs3; im = 3; }
        float sm = sigx(m);                         // == max of the 4 sigmoids
        int lab = im;
        if (im > 0) {                               // tie guard (first-argmax)
            float lim = m - 1e-4f;
            if (xs0 > lim || (im > 1 && xs1 > lim) || (im > 2 && xs2 > lim)) {
                if (xs0 > lim && sigx(xs0) == sm) lab = 0;
                else if (im > 1 && xs1 > lim && sigx(xs1) == sm) lab = 1;
                else if (im > 2 && xs2 > lim && sigx(xs2) == sm) lab = 2;
            }
        }
        float sctr  = sigx(ctrB[idx]);
        float score = __fsqrt_rn(__fmul_rn(sm, sctr));
        cand[p] = ((u64)__float_as_uint(score) << 32)
                | ((u64)(0x7FFFu - idx) << 4) | (u64)(lab + 1);
    }
    __syncthreads();

    // ---------------- Phase 5: bitonic sort (hybrid reg/smem) ----------------
    if (C <= 2048) {
        const int base = wid * 64;
        u64 r0 = (base + lane      < C) ? cand[base + lane]      : 0ULL;
        u64 r1 = (base + 32 + lane < C) ? cand[base + 32 + lane] : 0ULL;
        __syncthreads();
#pragma unroll
        for (int k2 = 2; k2 <= 16; k2 <<= 1) {
            bool up = ((lane & k2) == 0);
#pragma unroll
            for (int j = k2 >> 1; j > 0; j >>= 1) {
                r0 = cex_shfl(r0, j, up, lane);
                r1 = cex_shfl(r1, j, up, lane);
            }
        }
#pragma unroll
        for (int j = 16; j > 0; j >>= 1) {
            r0 = cex_shfl(r0, j, true,  lane);
            r1 = cex_shfl(r1, j, false, lane);
        }
        {
            bool up = ((base & 64) == 0);
            u64 lo = r0, hi = r1;
            if (up) { r0 = lo > hi ? lo : hi; r1 = lo > hi ? hi : lo; }
            else    { r0 = lo < hi ? lo : hi; r1 = lo < hi ? hi : lo; }
#pragma unroll
            for (int j = 16; j > 0; j >>= 1) {
                r0 = cex_shfl(r0, j, up, lane);
                r1 = cex_shfl(r1, j, up, lane);
            }
        }
        for (int k2 = 128; k2 <= 2048; k2 <<= 1) {
            cand[base + lane] = r0; cand[base + 32 + lane] = r1;
            __syncthreads();
            for (int j = k2 >> 1; j >= 64; j >>= 1) {
                for (int t = tid; t < 2048; t += NT) {
                    int ixj = t ^ j;
                    if (ixj > t) {
                        u64 a = cand[t], b2 = cand[ixj];
                        bool up = ((t & k2) == 0);
                        if (up ? (a < b2) : (a > b2)) { cand[t] = b2; cand[ixj] = a; }
                    }
                }
                __syncthreads();
            }
            r0 = cand[base + lane]; r1 = cand[base + 32 + lane];
            bool up = ((base & k2) == 0);
            u64 lo = r0, hi = r1;
            if (up) { r0 = lo > hi ? lo : hi; r1 = lo > hi ? hi : lo; }
            else    { r0 = lo < hi ? lo : hi; r1 = lo < hi ? hi : lo; }
#pragma unroll
            for (int j = 16; j > 0; j >>= 1) {
                r0 = cex_shfl(r0, j, up, lane);
                r1 = cex_shfl(r1, j, up, lane);
            }
        }
        cand[base + lane] = r0; cand[base + 32 + lane] = r1;
        __syncthreads();
    } else {
        for (int i = tid; i < CCAP; i += NT) if (i >= C) cand[i] = 0ULL;
        __syncthreads();
        for (int k2 = 2; k2 <= CCAP; k2 <<= 1)
            for (int j = k2 >> 1; j > 0; j >>= 1) {
                for (int t = tid; t < CCAP; t += NT) {
                    int ixj = t ^ j;
                    if (ixj > t) {
                        u64 a = cand[t], b2 = cand[ixj];
                        bool up = ((t & k2) == 0);
                        if (up ? (a < b2) : (a > b2)) { cand[t] = b2; cand[ixj] = a; }
                    }
                }
                __syncthreads();
            }
    }

    // ---------------- Phase 6: gather top-1000, boxes, offsets ---------------
    float x1 = 0, y1 = 0, x2 = 0, y2 = 0, score = 0;
    int label = 0; bool validf = false;
    if (tid < KTOP) {
        u64 key = cand[tid];
        score  = __uint_as_float((unsigned)(key >> 32));
        label  = (int)(key & 0xFull);
        int idx = 0x7FFF - (int)((key >> 4) & 0x7FFFull);
        validf = (score >= 0.05f);

        float4 r4 = ((const float4*)reg)[(size_t)b * NA + idx];
        float2 xy = ((const float2*)coords)[idx];
        float  st = pstr[idx];
        x1 = __fsub_rn(xy.x, __fmul_rn(r4.x, st));
        y1 = __fsub_rn(xy.y, __fmul_rn(r4.y, st));
        x2 = __fadd_rn(xy.x, __fmul_rn(r4.z, st));
        y2 = __fadd_rn(xy.y, __fmul_rn(r4.w, st));
        x1 = fminf(fmaxf(x1, 0.0f), 1023.0f);
        y1 = fminf(fmaxf(y1, 0.0f), 799.0f);
        x2 = fminf(fmaxf(x2, 0.0f), 1023.0f);
        y2 = fminf(fmaxf(y2, 0.0f), 799.0f);

        sbox[tid] = make_float4(x1, y1, x2, y2);
        ssc[tid]  = score;
        slab[tid] = (unsigned)label;
        sval[tid] = validf ? 1u : 0u;
    }

    float vmax = -1000000000.0f, vmin = 1000000000.0f;
    if (tid < KTOP && validf) {
        vmax = fmaxf(fmaxf(x1, y1), fmaxf(x2, y2));
        vmin = fminf(fminf(x1, y1), fminf(x2, y2));
    }
#pragma unroll
    for (int o = 16; o; o >>= 1) {
        vmax = fmaxf(vmax, __shfl_xor_sync(0xffffffffu, vmax, o));
        vmin = fminf(vmin, __shfl_xor_sync(0xffffffffu, vmin, o));
    }
    if (lane == 0) { redmax[wid] = vmax; redmin[wid] = vmin; }
    __syncthreads();
    if (tid == 0) {
        float mx = redmax[0], mn = redmin[0];
        for (int w = 1; w < 32; ++w) { mx = fmaxf(mx, redmax[w]); mn = fminf(mn, redmin[w]); }
        s_mx = mx; s_mn = mn;
    }
    __syncthreads();

    if (tid < KTOP) {
        float off = __fmul_rn((float)label, __fadd_rn(__fsub_rn(s_mx, s_mn), 1.0f));
        float a  = __fadd_rn(x1, off), bb = __fadd_rn(y1, off);
        float cc = __fadd_rn(x2, off), dd = __fadd_rn(y2, off);
        sx1[tid] = a;  sy1[tid] = bb;
        sx2[tid] = cc; sy2[tid] = dd;
        sar[tid] = __fmul_rn(__fsub_rn(cc, a), __fsub_rn(dd, bb));
    }
    __syncthreads();   // cand fully consumed; mat may now overwrite

    // ---------------- Phase 7: suppression bit-matrix (in smem) --------------
    for (int i = wid; i < KTOP; i += 32) {
        float ax1 = sx1[i], ay1 = sy1[i], ax2 = sx2[i], ay2 = sy2[i], aa = sar[i];
        unsigned myword = 0;
        for (int jc = 0; jc < 32; ++jc) {
            int jbase = jc * 32;
            unsigned wbits = 0;
            if (jbase + 31 > i) {
                int j = jbase + lane;
                bool sup = false;
                if (j > i && j < KTOP) {
                    float ix1 = fmaxf(ax1, sx1[j]);
                    float iy1 = fmaxf(ay1, sy1[j]);
                    float ix2 = fminf(ax2, sx2[j]);
                    float iy2 = fminf(ay2, sy2[j]);
                    float iw  = fmaxf(__fsub_rn(ix2, ix1), 0.0f);
                    float ih  = fmaxf(__fsub_rn(iy2, iy1), 0.0f);
                    float inter = __fmul_rn(iw, ih);
                    float uni = fmaxf(__fsub_rn(__fadd_rn(aa, sar[j]), inter), 1e-9f);
                    sup = __fdiv_rn(inter, uni) > 0.5f;
                }
                wbits = __ballot_sync(0xffffffffu, sup);
            }
            if (lane == jc) myword = wbits;
        }
        mat[i * 32 + lane] = myword;
    }
    __syncthreads();

    // ---------------- Phase 8: serial greedy NMS (warp 0, skip-based) --------
    if (wid == 0) {
        unsigned removed = 0;                       // lane owns [32*lane, 32*lane+32)
#pragma unroll
        for (int jj = 0; jj < 32; ++jj) {
            int j = lane * 32 + jj;
            removed |= (((j < KTOP) && sval[j]) ? 0u : 1u) << jj;
        }
        int cur = -1;
        while (true) {
            unsigned avail = ~removed;
            int curLane = cur >> 5;
            unsigned m;
            if (lane < curLane)       m = 0u;
            else if (lane == curLane) m = avail & (0xFFFFFFFEu << (cur & 31));
            else                      m = avail;
            unsigned bal = __ballot_sync(0xffffffffu, m != 0u);
            if (!bal) break;
            int src = __ffs(bal) - 1;
            unsigned mm = __shfl_sync(0xffffffffu, m, src);
            int i = src * 32 + __ffs(mm) - 1;       // next kept box
            removed |= mat[i * 32 + lane];
            cur = i;
        }
        srem[lane] = removed;
    }
    __syncthreads();

    // ---------------- Phase 9: outputs (scores | labels | boxes) -------------
    if (tid < KTOP) {
        bool k = ((srem[tid >> 5] >> (tid & 31)) & 1u) == 0u;
        float so = k ? ssc[tid] : 0.0f;
        float lo = k ? (float)slab[tid] : 0.0f;
        float4 bx = sbox[tid];
        if (!k) bx = make_float4(0.f, 0.f, 0.f, 0.f);
        out[(size_t)b * KTOP + tid] = so;
        out[(size_t)(B * KTOP) + (size_t)b * KTOP + tid] = lo;
        size_t base = (size_t)(2 * B * KTOP) + ((size_t)b * KTOP + tid) * 4;
        out[base + 0] = bx.x; out[base + 1] = bx.y;
        out[base + 2] = bx.z; out[base + 3] = bx.w;
    }
}

extern "C" void kernel_launch(void* const* d_in, const int* in_sizes, int n_in,
                              void* d_out, int out_size) {
    (void)in_sizes; (void)n_in; (void)out_size;
    static bool attr_done = false;
    if (!attr_done) {
        cudaFuncSetAttribute(fcos_all, cudaFuncAttributeMaxDynamicSharedMemorySize,
                             SMEM_TOTAL);
        attr_done = true;
    }
    fcos_all<<<B, NT, SMEM_TOTAL>>>(
        (const float*)d_in[0], (const float*)d_in[1], (const float*)d_in[2],
        (const float*)d_in[3], (const float*)d_in[4], (float*)d_out);
}

// round 6
// speedup vs baseline: 1.7671x; 1.7671x over previous
#include <cuda_runtime.h>
#include <cstdint>

#define NA     17064
#define KTOP   1000
#define NBINS  16384
#define CCAP   4096
#define NT     1024
#define B      16
#define NCTA   128          // 8 CTAs per batch, co-resident (1 CTA/SM)

typedef unsigned long long u64;

// ---------------- static device scratch ----------------
__device__ float    gscore[B][NA];
__device__ unsigned ghist[B][NBINS];      // zero-init; re-zeroed each pass
__device__ unsigned gcidx[B][CCAP];
__device__ unsigned gcnt[B];
__device__ u64      gkey[B][CCAP];
__device__ float    gssc[B][KTOP];
__device__ unsigned gslab[B][KTOP];
__device__ unsigned gsval[B][KTOP];
__device__ float4   gsbox[B][KTOP];
__device__ float    gsx1[B][KTOP], gsy1[B][KTOP], gsx2[B][KTOP],
                    gsy2[B][KTOP], gsar[B][KTOP];
__device__ unsigned gmat[B][KTOP][32];
__device__ unsigned gbar[8];              // epoch barrier counters (monotonic)

// Exact sigmoid: float exp via double exp (correctly rounded to float =>
// matches faithful libm expf), then float add + div as XLA expands logistic.
__device__ __forceinline__ float sigx(float x) {
    float t = (float)exp(-(double)x);
    return __fdiv_rn(1.0f, __fadd_rn(1.0f, t));
}
// Fast approximate sigmoid — superset selection only.
__device__ __forceinline__ float siga(float x) {
    return __fdividef(1.0f, 1.0f + __expf(-x));
}
// compare-exchange via shfl (bitonic)
__device__ __forceinline__ u64 cex_shfl(u64 v, int j, bool up, int lane) {
    u64 p = __shfl_xor_sync(0xffffffffu, v, j);
    bool lower = ((lane & j) == 0);
    return (lower == up) ? (v > p ? v : p) : (v < p ? v : p);
}
// grid-wide barrier, epoch-based (safe across graph replays, no reset)
__device__ __forceinline__ void gbarrier(int k) {
    __syncthreads();
    if (threadIdx.x == 0) {
        __threadfence();
        unsigned old   = atomicAdd(&gbar[k], 1u);
        unsigned epoch = old / NCTA;
        volatile unsigned* p = &gbar[k];
        while (*p < (epoch + 1u) * NCTA) __nanosleep(32);
        __threadfence();
    }
    __syncthreads();
}

#define OFF_SVAL   128000
#define SMEM_TOTAL 132096   // max(32KB sort, 20KB boxes, 128KB mat + 4KB sval)

extern __shared__ unsigned char smem_raw[];

__global__ void __launch_bounds__(NT, 1)
fcos_persist(const float* __restrict__ cls, const float* __restrict__ ctr,
             const float* __restrict__ reg, const float* __restrict__ coords,
             const float* __restrict__ pstr, float* __restrict__ out)
{
    const int cta  = blockIdx.x;
    const int b    = cta >> 3;          // batch
    const int r    = cta & 7;           // sub-CTA within batch
    const int tid  = threadIdx.x;
    const int lane = tid & 31;
    const int wid  = tid >> 5;

    __shared__ unsigned chunk[1024];
    __shared__ unsigned super[32];
    __shared__ float redmax[32], redmin[32];
    __shared__ float s_mx, s_mn;
    __shared__ unsigned s_thr, srem[32];

    const float4* clsB = (const float4*)cls + (size_t)b * NA;
    const float*  ctrB = ctr + (size_t)b * NA;

    // ============ Phase 1: approx scores + global histogram (128 CTAs) ======
    if (r == 0 && tid == 0) gcnt[b] = 0;
    for (int i = r * NT + tid; i < NA; i += 8 * NT) {
        float4 c = clsB[i];
        float m = fmaxf(fmaxf(c.x, c.y), fmaxf(c.z, c.w));   // sigmoid monotone
        float score = __fsqrt_rn(siga(m) * siga(ctrB[i]));
        gscore[b][i] = score;
        atomicAdd(&ghist[b][__float_as_uint(score) >> 16], 1u);
    }
    gbarrier(0);

    // ============ Phase 2: threshold (redundant per CTA) + compact ==========
    { unsigned s = 0; int base = tid * 16;
#pragma unroll
      for (int q = 0; q < 16; ++q) s += ghist[b][base + q];
      chunk[tid] = s; }
    __syncthreads();
    { unsigned s = chunk[wid * 32 + lane];            // warp w reduces 32 chunks
#pragma unroll
      for (int o = 16; o; o >>= 1) s += __shfl_xor_sync(0xffffffffu, s, o);
      if (lane == 0) super[wid] = s; }
    __syncthreads();
    if (tid == 0) {
        unsigned acc = 0; int T = 0;
        for (int sblk = 31; sblk >= 0; --sblk) {
            if (acc + super[sblk] >= KTOP) {
                for (int c = sblk * 32 + 31; c >= sblk * 32; --c) {
                    if (acc + chunk[c] >= KTOP) {
                        for (int bin = c * 16 + 15; bin >= c * 16; --bin) {
                            acc += ghist[b][bin];
                            if (acc >= KTOP) { T = bin; break; }
                        }
                        break;
                    }
                    acc += chunk[c];
                }
                break;
            }
            acc += super[sblk];
        }
        s_thr = (unsigned)(T > 0 ? T - 1 : 0);   // one-bin superset margin
    }
    __syncthreads();
    const unsigned T = s_thr;

    for (int i = r * NT + tid; i < NA; i += 8 * NT) {
        if ((__float_as_uint(gscore[b][i]) >> 16) >= T) {
            unsigned p = atomicAdd(&gcnt[b], 1u);
            if (p < CCAP) gcidx[b][p] = (unsigned)i;
        }
    }
    gbarrier(1);

    // ============ Phase 3: exact rescore (8 CTAs/batch) + ghist re-zero =====
    int C = (int)gcnt[b]; if (C > CCAP) C = CCAP;
    for (int p = r * NT + tid; p < C; p += 8 * NT) {
        unsigned idx = gcidx[b][p];
        float4 c = clsB[idx];
        float xs0 = c.x, xs1 = c.y, xs2 = c.z, xs3 = c.w;
        float m = xs0; int im = 0;
        if (xs1 > m) { m = xs1; im = 1; }
        if (xs2 > m) { m = xs2; im = 2; }
        if (xs3 > m) { m = xs3; im = 3; }
        float sm = sigx(m);                         // == max of the 4 sigmoids
        int lab = im;
        if (im > 0) {                               // tie guard (first-argmax)
            float lim = m - 1e-4f;
            if (xs0 > lim || (im > 1 && xs1 > lim) || (im > 2 && xs2 > lim)) {
                if (xs0 > lim && sigx(xs0) == sm) lab = 0;
                else if (im > 1 && xs1 > lim && sigx(xs1) == sm) lab = 1;
                else if (im > 2 && xs2 > lim && sigx(xs2) == sm) lab = 2;
            }
        }
        float sctr  = sigx(ctrB[idx]);
        float score = __fsqrt_rn(__fmul_rn(sm, sctr));
        gkey[b][p] = ((u64)__float_as_uint(score) << 32)
                   | ((u64)(0x7FFFu - idx) << 4) | (u64)(lab + 1);
    }
    for (int i = r * 2048 + tid; i < (r + 1) * 2048; i += NT)   // re-zero hist
        ghist[b][i] = 0;
    gbarrier(2);

    // ============ Phase 4: sort + box build (1 CTA/batch) ==================
    if (r == 0) {
        u64* cand = (u64*)smem_raw;
        if (C <= 2048) {
            const int base = wid * 64;
            u64 r0 = (base + lane      < C) ? gkey[b][base + lane]      : 0ULL;
            u64 r1 = (base + 32 + lane < C) ? gkey[b][base + 32 + lane] : 0ULL;
#pragma unroll
            for (int k2 = 2; k2 <= 16; k2 <<= 1) {
                bool up = ((lane & k2) == 0);
#pragma unroll
                for (int j = k2 >> 1; j > 0; j >>= 1) {
                    r0 = cex_shfl(r0, j, up, lane);
                    r1 = cex_shfl(r1, j, up, lane);
                }
            }
#pragma unroll
            for (int j = 16; j > 0; j >>= 1) {
                r0 = cex_shfl(r0, j, true,  lane);
                r1 = cex_shfl(r1, j, false, lane);
            }
            {
                bool up = ((base & 64) == 0);
                u64 lo = r0, hi = r1;
                if (up) { r0 = lo > hi ? lo : hi; r1 = lo > hi ? hi : lo; }
                else    { r0 = lo < hi ? lo : hi; r1 = lo < hi ? hi : lo; }
#pragma unroll
                for (int j = 16; j > 0; j >>= 1) {
                    r0 = cex_shfl(r0, j, up, lane);
                    r1 = cex_shfl(r1, j, up, lane);
                }
            }
            for (int k2 = 128; k2 <= 2048; k2 <<= 1) {
                cand[base + lane] = r0; cand[base + 32 + lane] = r1;
                __syncthreads();
                for (int j = k2 >> 1; j >= 64; j >>= 1) {
                    for (int t = tid; t < 2048; t += NT) {
                        int ixj = t ^ j;
                        if (ixj > t) {
                            u64 a = cand[t], b2 = cand[ixj];
                            bool up = ((t & k2) == 0);
                            if (up ? (a < b2) : (a > b2)) { cand[t] = b2; cand[ixj] = a; }
                        }
                    }
                    __syncthreads();
                }
                r0 = cand[base + lane]; r1 = cand[base + 32 + lane];
                bool up = ((base & k2) == 0);
                u64 lo = r0, hi = r1;
                if (up) { r0 = lo > hi ? lo : hi; r1 = lo > hi ? hi : lo; }
                else    { r0 = lo < hi ? lo : hi; r1 = lo < hi ? hi : lo; }
#pragma unroll
                for (int j = 16; j > 0; j >>= 1) {
                    r0 = cex_shfl(r0, j, up, lane);
                    r1 = cex_shfl(r1, j, up, lane);
                }
            }
            cand[base + lane] = r0; cand[base + 32 + lane] = r1;
            __syncthreads();
        } else {
            for (int i = tid; i < CCAP; i += NT)
                cand[i] = (i < C) ? gkey[b][i] : 0ULL;
            __syncthreads();
            for (int k2 = 2; k2 <= CCAP; k2 <<= 1)
                for (int j = k2 >> 1; j > 0; j >>= 1) {
                    for (int t = tid; t < CCAP; t += NT) {
                        int ixj = t ^ j;
                        if (ixj > t) {
                            u64 a = cand[t], b2 = cand[ixj];
                            bool up = ((t & k2) == 0);
                            if (up ? (a < b2) : (a > b2)) { cand[t] = b2; cand[ixj] = a; }
                        }
                    }
                    __syncthreads();
                }
        }

        // gather top-1000, build boxes
        float x1 = 0, y1 = 0, x2 = 0, y2 = 0, score = 0;
        int label = 0; bool validf = false;
        if (tid < KTOP) {
            u64 key = cand[tid];
            score  = __uint_as_float((unsigned)(key >> 32));
            label  = (int)(key & 0xFull);
            int idx = 0x7FFF - (int)((key >> 4) & 0x7FFFull);
            validf = (score >= 0.05f);

            float4 r4 = ((const float4*)reg)[(size_t)b * NA + idx];
            float2 xy = ((const float2*)coords)[idx];
            float  st = pstr[idx];
            x1 = __fsub_rn(xy.x, __fmul_rn(r4.x, st));
            y1 = __fsub_rn(xy.y, __fmul_rn(r4.y, st));
            x2 = __fadd_rn(xy.x, __fmul_rn(r4.z, st));
            y2 = __fadd_rn(xy.y, __fmul_rn(r4.w, st));
            x1 = fminf(fmaxf(x1, 0.0f), 1023.0f);
            y1 = fminf(fmaxf(y1, 0.0f), 799.0f);
            x2 = fminf(fmaxf(x2, 0.0f), 1023.0f);
            y2 = fminf(fmaxf(y2, 0.0f), 799.0f);

            gsbox[b][tid] = make_float4(x1, y1, x2, y2);
            gssc[b][tid]  = score;
            gslab[b][tid] = (unsigned)label;
            gsval[b][tid] = validf ? 1u : 0u;
        }

        float vmax = -1000000000.0f, vmin = 1000000000.0f;
        if (tid < KTOP && validf) {
            vmax = fmaxf(fmaxf(x1, y1), fmaxf(x2, y2));
            vmin = fminf(fminf(x1, y1), fminf(x2, y2));
        }
#pragma unroll
        for (int o = 16; o; o >>= 1) {
            vmax = fmaxf(vmax, __shfl_xor_sync(0xffffffffu, vmax, o));
            vmin = fminf(vmin, __shfl_xor_sync(0xffffffffu, vmin, o));
        }
        if (lane == 0) { redmax[wid] = vmax; redmin[wid] = vmin; }
        __syncthreads();
        if (tid == 0) {
            float mx = redmax[0], mn = redmin[0];
            for (int w = 1; w < 32; ++w) { mx = fmaxf(mx, redmax[w]); mn = fminf(mn, redmin[w]); }
            s_mx = mx; s_mn = mn;
        }
        __syncthreads();

        if (tid < KTOP) {
            float off = __fmul_rn((float)label, __fadd_rn(__fsub_rn(s_mx, s_mn), 1.0f));
            float a  = __fadd_rn(x1, off), bb = __fadd_rn(y1, off);
            float cc = __fadd_rn(x2, off), dd = __fadd_rn(y2, off);
            gsx1[b][tid] = a;  gsy1[b][tid] = bb;
            gsx2[b][tid] = cc; gsy2[b][tid] = dd;
            gsar[b][tid] = __fmul_rn(__fsub_rn(cc, a), __fsub_rn(dd, bb));
        }
    }
    gbarrier(3);

    // ============ Phase 5: suppression bit-matrix (8 CTAs/batch) ============
    {
        float* sx1 = (float*)smem_raw;
        float* sy1 = sx1 + KTOP; float* sx2 = sy1 + KTOP;
        float* sy2 = sx2 + KTOP; float* sar = sy2 + KTOP;
        for (int j = tid; j < KTOP; j += NT) {
            sx1[j] = gsx1[b][j]; sy1[j] = gsy1[b][j];
            sx2[j] = gsx2[b][j]; sy2[j] = gsy2[b][j];
            sar[j] = gsar[b][j];
        }
        __syncthreads();

        int i0 = r * 125, i1 = i0 + 125;
        for (int i = i0 + wid; i < i1; i += 32) {
            float ax1 = sx1[i], ay1 = sy1[i], ax2 = sx2[i], ay2 = sy2[i], aa = sar[i];
            unsigned myword = 0;
            for (int jc = 0; jc < 32; ++jc) {
                int jbase = jc * 32;
                unsigned wbits = 0;
                if (jbase + 31 > i) {
                    int j = jbase + lane;
                    bool sup = false;
                    if (j > i && j < KTOP) {
                        float ix1 = fmaxf(ax1, sx1[j]);
                        float iy1 = fmaxf(ay1, sy1[j]);
                        float ix2 = fminf(ax2, sx2[j]);
                        float iy2 = fminf(ay2, sy2[j]);
                        float iw  = fmaxf(__fsub_rn(ix2, ix1), 0.0f);
                        float ih  = fmaxf(__fsub_rn(iy2, iy1), 0.0f);
                        float inter = __fmul_rn(iw, ih);
                        float uni = fmaxf(__fsub_rn(__fadd_rn(aa, sar[j]), inter), 1e-9f);
                        sup = __fdiv_rn(inter, uni) > 0.5f;
                    }
                    wbits = __ballot_sync(0xffffffffu, sup);
                }
                if (lane == jc) myword = wbits;
            }
            gmat[b][i][lane] = myword;
        }
    }
    gbarrier(4);

    // ============ Phase 6: serial greedy NMS + outputs (1 CTA/batch) ========
    if (r != 0) return;
    {
        unsigned* smat  = (unsigned*)smem_raw;          // 32000 u32
        unsigned* ssval = (unsigned*)(smem_raw + OFF_SVAL);
        const uint4* src = (const uint4*)&gmat[b][0][0];
        uint4* dst = (uint4*)smat;
        for (int t = tid; t < KTOP * 8; t += NT) dst[t] = src[t];
        ssval[tid] = (tid < KTOP) ? gsval[b][tid] : 0u;
        __syncthreads();

        if (wid == 0) {
            unsigned removed = 0;                       // lane owns [32*lane, +32)
#pragma unroll
            for (int jj = 0; jj < 32; ++jj)
                removed |= (ssval[lane * 32 + jj] ? 0u : 1u) << jj;

            int cur = -1;
            while (true) {
                unsigned avail = ~removed;
                int curLane = cur >> 5;
                unsigned m;
                if (lane < curLane)       m = 0u;
                else if (lane == curLane) m = avail & (0xFFFFFFFEu << (cur & 31));
                else                      m = avail;
                unsigned bal = __ballot_sync(0xffffffffu, m != 0u);
                if (!bal) break;
                int s2 = __ffs(bal) - 1;
                unsigned mm = __shfl_sync(0xffffffffu, m, s2);
                int i = s2 * 32 + __ffs(mm) - 1;        // next kept box
                removed |= smat[i * 32 + lane];
                cur = i;
            }
            srem[lane] = removed;
        }
        __syncthreads();

        if (tid < KTOP) {
            bool k = ((srem[tid >> 5] >> (tid & 31)) & 1u) == 0u;
            float so = k ? gssc[b][tid] : 0.0f;
            float lo = k ? (float)gslab[b][tid] : 0.0f;
            float4 bx = gsbox[b][tid];
            if (!k) bx = make_float4(0.f, 0.f, 0.f, 0.f);
            out[(size_t)b * KTOP + tid] = so;
            out[(size_t)(B * KTOP) + (size_t)b * KTOP + tid] = lo;
            size_t base = (size_t)(2 * B * KTOP) + ((size_t)b * KTOP + tid) * 4;
            out[base + 0] = bx.x; out[base + 1] = bx.y;
            out[base + 2] = bx.z; out[base + 3] = bx.w;
        }
    }
}

extern "C" void kernel_launch(void* const* d_in, const int* in_sizes, int n_in,
                              void* d_out, int out_size) {
    (void)in_sizes; (void)n_in; (void)out_size;
    static bool attr_done = false;
    if (!attr_done) {
        cudaFuncSetAttribute(fcos_persist, cudaFuncAttributeMaxDynamicSharedMemorySize,
                             SMEM_TOTAL);
        attr_done = true;
    }
    fcos_persist<<<NCTA, NT, SMEM_TOTAL>>>(
        (const float*)d_in[0], (const float*)d_in[1], (const float*)d_in[2],
        (const float*)d_in[3], (const float*)d_in[4], (float*)d_out);
}

// round 7
// speedup vs baseline: 3.2111x; 1.8172x over previous
#include <cuda_runtime.h>
#include <cstdint>

#define NA     17064
#define KTOP   1000
#define NBINS  16384
#define CCAP   4096
#define NT     1024
#define B      16
#define NCTA   128          // 8 CTAs per batch, co-resident (1 CTA/SM)

typedef unsigned long long u64;

// ---------------- static device scratch ----------------
__device__ float    gscore[B][NA];
__device__ unsigned ghist[B][NBINS];      // zero-init; re-zeroed each pass
__device__ unsigned gcidx[B][CCAP];
__device__ unsigned gcnt[B];
__device__ u64      gkey[B][CCAP];
__device__ float    gssc[B][KTOP];
__device__ unsigned gslab[B][KTOP];
__device__ unsigned gvbits[B][32];        // validity bitmask (ballot words)
__device__ float4   gsbox[B][KTOP];
__device__ float    gsx1[B][KTOP], gsy1[B][KTOP], gsx2[B][KTOP],
                    gsy2[B][KTOP], gsar[B][KTOP];
__device__ unsigned gmat[B][KTOP][32];
__device__ unsigned gbar[8];              // epoch barrier counters (monotonic)

// Exact sigmoid: float exp via double exp (correctly rounded to float =>
// matches faithful libm expf), then float add + div as XLA expands logistic.
__device__ __forceinline__ float sigx(float x) {
    float t = (float)exp(-(double)x);
    return __fdiv_rn(1.0f, __fadd_rn(1.0f, t));
}
// Fast approximate sigmoid — superset selection only.
__device__ __forceinline__ float siga(float x) {
    return __fdividef(1.0f, 1.0f + __expf(-x));
}
// compare-exchange via shfl (bitonic)
__device__ __forceinline__ u64 cex_shfl(u64 v, int j, bool up, int lane) {
    u64 p = __shfl_xor_sync(0xffffffffu, v, j);
    bool lower = ((lane & j) == 0);
    return (lower == up) ? (v > p ? v : p) : (v < p ? v : p);
}
// grid-wide barrier, epoch-based (safe across graph replays, no reset)
__device__ __forceinline__ void gbarrier(int k) {
    __syncthreads();
    if (threadIdx.x == 0) {
        __threadfence();
        unsigned old   = atomicAdd(&gbar[k], 1u);
        unsigned epoch = old / NCTA;
        volatile unsigned* p = &gbar[k];
        while (*p < (epoch + 1u) * NCTA) __nanosleep(32);
        __threadfence();
    }
    __syncthreads();
}

#define OFF_SDIAG  128000
#define SMEM_TOTAL 132096   // max(32KB sort, 20KB boxes, 125KB mat + 4KB sdiag)

extern __shared__ unsigned char smem_raw[];

__global__ void __launch_bounds__(NT, 1)
fcos_persist(const float* __restrict__ cls, const float* __restrict__ ctr,
             const float* __restrict__ reg, const float* __restrict__ coords,
             const float* __restrict__ pstr, float* __restrict__ out)
{
    const int cta  = blockIdx.x;
    const int b    = cta >> 3;          // batch
    const int r    = cta & 7;           // sub-CTA within batch
    const int tid  = threadIdx.x;
    const int lane = tid & 31;
    const int wid  = tid >> 5;

    __shared__ unsigned chunk[1024];
    __shared__ unsigned super[32];
    __shared__ float redmax[32], redmin[32];
    __shared__ float s_mx, s_mn;
    __shared__ unsigned s_thr, srem[32];

    const float4* clsB = (const float4*)cls + (size_t)b * NA;
    const float*  ctrB = ctr + (size_t)b * NA;

    // ============ Phase 1: approx scores + global histogram (128 CTAs) ======
    if (r == 0 && tid == 0) gcnt[b] = 0;
    for (int i = r * NT + tid; i < NA; i += 8 * NT) {
        float4 c = clsB[i];
        float m = fmaxf(fmaxf(c.x, c.y), fmaxf(c.z, c.w));   // sigmoid monotone
        float score = __fsqrt_rn(siga(m) * siga(ctrB[i]));
        gscore[b][i] = score;
        atomicAdd(&ghist[b][__float_as_uint(score) >> 16], 1u);
    }
    gbarrier(0);

    // ============ Phase 2: threshold (redundant per CTA) + compact ==========
    { unsigned s = 0; int base = tid * 16;
#pragma unroll
      for (int q = 0; q < 16; ++q) s += ghist[b][base + q];
      chunk[tid] = s; }
    __syncthreads();
    { unsigned s = chunk[wid * 32 + lane];
#pragma unroll
      for (int o = 16; o; o >>= 1) s += __shfl_xor_sync(0xffffffffu, s, o);
      if (lane == 0) super[wid] = s; }
    __syncthreads();
    if (tid == 0) {
        unsigned acc = 0; int T = 0;
        for (int sblk = 31; sblk >= 0; --sblk) {
            if (acc + super[sblk] >= KTOP) {
                for (int c = sblk * 32 + 31; c >= sblk * 32; --c) {
                    if (acc + chunk[c] >= KTOP) {
                        for (int bin = c * 16 + 15; bin >= c * 16; --bin) {
                            acc += ghist[b][bin];
                            if (acc >= KTOP) { T = bin; break; }
                        }
                        break;
                    }
                    acc += chunk[c];
                }
                break;
            }
            acc += super[sblk];
        }
        s_thr = (unsigned)(T > 0 ? T - 1 : 0);   // one-bin superset margin
    }
    __syncthreads();
    const unsigned T = s_thr;

    for (int i = r * NT + tid; i < NA; i += 8 * NT) {
        if ((__float_as_uint(gscore[b][i]) >> 16) >= T) {
            unsigned p = atomicAdd(&gcnt[b], 1u);
            if (p < CCAP) gcidx[b][p] = (unsigned)i;
        }
    }
    gbarrier(1);

    // ============ Phase 3: exact rescore (8 CTAs/batch) + ghist re-zero =====
    int C = (int)gcnt[b]; if (C > CCAP) C = CCAP;
    for (int p = r * NT + tid; p < C; p += 8 * NT) {
        unsigned idx = gcidx[b][p];
        float4 c = clsB[idx];
        float xs0 = c.x, xs1 = c.y, xs2 = c.z, xs3 = c.w;
        float m = xs0; int im = 0;
        if (xs1 > m) { m = xs1; im = 1; }
        if (xs2 > m) { m = xs2; im = 2; }
        if (xs3 > m) { m = xs3; im = 3; }
        float sm = sigx(m);                         // == max of the 4 sigmoids
        int lab = im;
        if (im > 0) {                               // tie guard (first-argmax)
            float lim = m - 1e-4f;
            if (xs0 > lim || (im > 1 && xs1 > lim) || (im > 2 && xs2 > lim)) {
                if (xs0 > lim && sigx(xs0) == sm) lab = 0;
                else if (im > 1 && xs1 > lim && sigx(xs1) == sm) lab = 1;
                else if (im > 2 && xs2 > lim && sigx(xs2) == sm) lab = 2;
            }
        }
        float sctr  = sigx(ctrB[idx]);
        float score = __fsqrt_rn(__fmul_rn(sm, sctr));
        gkey[b][p] = ((u64)__float_as_uint(score) << 32)
                   | ((u64)(0x7FFFu - idx) << 4) | (u64)(lab + 1);
    }
    for (int i = r * 2048 + tid; i < (r + 1) * 2048; i += NT)   // re-zero hist
        ghist[b][i] = 0;
    gbarrier(2);

    // ============ Phase 4: sort + box build (1 CTA/batch) ==================
    if (r == 0) {
        u64* cand = (u64*)smem_raw;
        if (C <= 2048) {
            const int base = wid * 64;
            u64 r0 = (base + lane      < C) ? gkey[b][base + lane]      : 0ULL;
            u64 r1 = (base + 32 + lane < C) ? gkey[b][base + 32 + lane] : 0ULL;
#pragma unroll
            for (int k2 = 2; k2 <= 16; k2 <<= 1) {
                bool up = ((lane & k2) == 0);
#pragma unroll
                for (int j = k2 >> 1; j > 0; j >>= 1) {
                    r0 = cex_shfl(r0, j, up, lane);
                    r1 = cex_shfl(r1, j, up, lane);
                }
            }
#pragma unroll
            for (int j = 16; j > 0; j >>= 1) {
                r0 = cex_shfl(r0, j, true,  lane);
                r1 = cex_shfl(r1, j, false, lane);
            }
            {
                bool up = ((base & 64) == 0);
                u64 lo = r0, hi = r1;
                if (up) { r0 = lo > hi ? lo : hi; r1 = lo > hi ? hi : lo; }
                else    { r0 = lo < hi ? lo : hi; r1 = lo < hi ? hi : lo; }
#pragma unroll
                for (int j = 16; j > 0; j >>= 1) {
                    r0 = cex_shfl(r0, j, up, lane);
                    r1 = cex_shfl(r1, j, up, lane);
                }
            }
            for (int k2 = 128; k2 <= 2048; k2 <<= 1) {
                cand[base + lane] = r0; cand[base + 32 + lane] = r1;
                __syncthreads();
                for (int j = k2 >> 1; j >= 64; j >>= 1) {
                    for (int t = tid; t < 2048; t += NT) {
                        int ixj = t ^ j;
                        if (ixj > t) {
                            u64 a = cand[t], b2 = cand[ixj];
                            bool up = ((t & k2) == 0);
                            if (up ? (a < b2) : (a > b2)) { cand[t] = b2; cand[ixj] = a; }
                        }
                    }
                    __syncthreads();
                }
                r0 = cand[base + lane]; r1 = cand[base + 32 + lane];
                bool up = ((base & k2) == 0);
                u64 lo = r0, hi = r1;
                if (up) { r0 = lo > hi ? lo : hi; r1 = lo > hi ? hi : lo; }
                else    { r0 = lo < hi ? lo : hi; r1 = lo < hi ? hi : lo; }
#pragma unroll
                for (int j = 16; j > 0; j >>= 1) {
                    r0 = cex_shfl(r0, j, up, lane);
                    r1 = cex_shfl(r1, j, up, lane);
                }
            }
            cand[base + lane] = r0; cand[base + 32 + lane] = r1;
            __syncthreads();
        } else {
            for (int i = tid; i < CCAP; i += NT)
                cand[i] = (i < C) ? gkey[b][i] : 0ULL;
            __syncthreads();
            for (int k2 = 2; k2 <= CCAP; k2 <<= 1)
                for (int j = k2 >> 1; j > 0; j >>= 1) {
                    for (int t = tid; t < CCAP; t += NT) {
                        int ixj = t ^ j;
                        if (ixj > t) {
                            u64 a = cand[t], b2 = cand[ixj];
                            bool up = ((t & k2) == 0);
                            if (up ? (a < b2) : (a > b2)) { cand[t] = b2; cand[ixj] = a; }
                        }
                    }
                    __syncthreads();
                }
        }

        // gather top-1000, build boxes
        float x1 = 0, y1 = 0, x2 = 0, y2 = 0, score = 0;
        int label = 0; bool validf = false;
        if (tid < KTOP) {
            u64 key = cand[tid];
            score  = __uint_as_float((unsigned)(key >> 32));
            label  = (int)(key & 0xFull);
            int idx = 0x7FFF - (int)((key >> 4) & 0x7FFFull);
            validf = (score >= 0.05f);

            float4 r4 = ((const float4*)reg)[(size_t)b * NA + idx];
            float2 xy = ((const float2*)coords)[idx];
            float  st = pstr[idx];
            x1 = __fsub_rn(xy.x, __fmul_rn(r4.x, st));
            y1 = __fsub_rn(xy.y, __fmul_rn(r4.y, st));
            x2 = __fadd_rn(xy.x, __fmul_rn(r4.z, st));
            y2 = __fadd_rn(xy.y, __fmul_rn(r4.w, st));
            x1 = fminf(fmaxf(x1, 0.0f), 1023.0f);
            y1 = fminf(fmaxf(y1, 0.0f), 799.0f);
            x2 = fminf(fmaxf(x2, 0.0f), 1023.0f);
            y2 = fminf(fmaxf(y2, 0.0f), 799.0f);

            gsbox[b][tid] = make_float4(x1, y1, x2, y2);
            gssc[b][tid]  = score;
            gslab[b][tid] = (unsigned)label;
        }
        // validity bitmask via ballot (warp w covers boxes 32w..32w+31)
        { unsigned vb = __ballot_sync(0xffffffffu, validf);
          if (lane == 0) gvbits[b][wid] = vb; }

        float vmax = -1000000000.0f, vmin = 1000000000.0f;
        if (tid < KTOP && validf) {
            vmax = fmaxf(fmaxf(x1, y1), fmaxf(x2, y2));
            vmin = fminf(fminf(x1, y1), fminf(x2, y2));
        }
#pragma unroll
        for (int o = 16; o; o >>= 1) {
            vmax = fmaxf(vmax, __shfl_xor_sync(0xffffffffu, vmax, o));
            vmin = fminf(vmin, __shfl_xor_sync(0xffffffffu, vmin, o));
        }
        if (lane == 0) { redmax[wid] = vmax; redmin[wid] = vmin; }
        __syncthreads();
        if (tid == 0) {
            float mx = redmax[0], mn = redmin[0];
            for (int w = 1; w < 32; ++w) { mx = fmaxf(mx, redmax[w]); mn = fminf(mn, redmin[w]); }
            s_mx = mx; s_mn = mn;
        }
        __syncthreads();

        if (tid < KTOP) {
            float off = __fmul_rn((float)label, __fadd_rn(__fsub_rn(s_mx, s_mn), 1.0f));
            float a  = __fadd_rn(x1, off), bb = __fadd_rn(y1, off);
            float cc = __fadd_rn(x2, off), dd = __fadd_rn(y2, off);
            gsx1[b][tid] = a;  gsy1[b][tid] = bb;
            gsx2[b][tid] = cc; gsy2[b][tid] = dd;
            gsar[b][tid] = __fmul_rn(__fsub_rn(cc, a), __fsub_rn(dd, bb));
        }
    }
    gbarrier(3);

    // ============ Phase 5: bit-matrix, rows interleaved (8 CTAs/batch) ======
    {
        float* sx1 = (float*)smem_raw;
        float* sy1 = sx1 + KTOP; float* sx2 = sy1 + KTOP;
        float* sy2 = sx2 + KTOP; float* sar = sy2 + KTOP;
        for (int j = tid; j < KTOP; j += NT) {
            sx1[j] = gsx1[b][j]; sy1[j] = gsy1[b][j];
            sx2[j] = gsx2[b][j]; sy2[j] = gsy2[b][j];
            sar[j] = gsar[b][j];
        }
        __syncthreads();

        for (int k = wid; k < 125; k += 32) {
            int i = r + 8 * k;                       // interleaved -> balanced
            float ax1 = sx1[i], ay1 = sy1[i], ax2 = sx2[i], ay2 = sy2[i], aa = sar[i];
            unsigned myword = 0;
            int jc0 = (i + 1) >> 5;
            for (int jc = jc0; jc < 32; ++jc) {      // uniform per warp
                int j = jc * 32 + lane;
                bool sup = false;
                if (j > i && j < KTOP) {
                    float ix1 = fmaxf(ax1, sx1[j]);
                    float iy1 = fmaxf(ay1, sy1[j]);
                    float ix2 = fminf(ax2, sx2[j]);
                    float iy2 = fminf(ay2, sy2[j]);
                    float iw  = fmaxf(__fsub_rn(ix2, ix1), 0.0f);
                    float ih  = fmaxf(__fsub_rn(iy2, iy1), 0.0f);
                    float inter = __fmul_rn(iw, ih);
                    float uni = fmaxf(__fsub_rn(__fadd_rn(aa, sar[j]), inter), 1e-9f);
                    sup = __fdiv_rn(inter, uni) > 0.5f;
                }
                unsigned wbits = __ballot_sync(0xffffffffu, sup);
                if (lane == jc) myword = wbits;
            }
            gmat[b][i][lane] = myword;
        }
    }
    gbarrier(4);

    // ============ Phase 6: block-serial NMS + outputs (1 CTA/batch) =========
    if (r != 0) return;
    {
        unsigned* smat  = (unsigned*)smem_raw;              // [1000][32]
        unsigned* sdiag = (unsigned*)(smem_raw + OFF_SDIAG);// [1024]
        { const uint4* src = (const uint4*)&gmat[b][0][0];
          uint4* dst = (uint4*)smat;
          for (int t = tid; t < KTOP * 8; t += NT) dst[t] = src[t]; }
        for (int i = tid; i < KTOP; i += NT) sdiag[i] = gmat[b][i][i >> 5];
        if (tid >= KTOP) sdiag[tid] = 0u;
        __syncthreads();

        if (wid == 0) {
            unsigned removed = ~gvbits[b][lane];   // lane owns [32*lane, +32)
            for (int bk = 0; bk < 32; ++bk) {
                unsigned curw = __shfl_sync(0xffffffffu, removed, bk);
                unsigned kept = 0;
                if (lane == 0) {
                    const uint4* dg = (const uint4*)(sdiag + bk * 32);
                    unsigned rem = curw;
#pragma unroll
                    for (int q = 0; q < 8; ++q) {
                        uint4 v = dg[q];
                        int j0 = q * 4;
                        if (!((rem >> (j0 + 0)) & 1u)) { kept |= 1u << (j0 + 0); rem |= v.x; }
                        if (!((rem >> (j0 + 1)) & 1u)) { kept |= 1u << (j0 + 1); rem |= v.y; }
                        if (!((rem >> (j0 + 2)) & 1u)) { kept |= 1u << (j0 + 2); rem |= v.z; }
                        if (!((rem >> (j0 + 3)) & 1u)) { kept |= 1u << (j0 + 3); rem |= v.w; }
                    }
                }
                kept = __shfl_sync(0xffffffffu, kept, 0);
#pragma unroll 4
                for (int jj = 0; jj < 32; ++jj) {
                    if ((kept >> jj) & 1u)                 // uniform branch
                        removed |= smat[(bk * 32 + jj) * 32 + lane];
                }
            }
            srem[lane] = removed;
        }
        __syncthreads();

        if (tid < KTOP) {
            bool k = ((srem[tid >> 5] >> (tid & 31)) & 1u) == 0u;
            float so = k ? gssc[b][tid] : 0.0f;
            float lo = k ? (float)gslab[b][tid] : 0.0f;
            float4 bx = gsbox[b][tid];
            if (!k) bx = make_float4(0.f, 0.f, 0.f, 0.f);
            out[(size_t)b * KTOP + tid] = so;
            out[(size_t)(B * KTOP) + (size_t)b * KTOP + tid] = lo;
            size_t base = (size_t)(2 * B * KTOP) + ((size_t)b * KTOP + tid) * 4;
            out[base + 0] = bx.x; out[base + 1] = bx.y;
            out[base + 2] = bx.z; out[base + 3] = bx.w;
        }
    }
}

extern "C" void kernel_launch(void* const* d_in, const int* in_sizes, int n_in,
                              void* d_out, int out_size) {
    (void)in_sizes; (void)n_in; (void)out_size;
    static bool attr_done = false;
    if (!attr_done) {
        cudaFuncSetAttribute(fcos_persist, cudaFuncAttributeMaxDynamicSharedMemorySize,
                             SMEM_TOTAL);
        attr_done = true;
    }
    fcos_persist<<<NCTA, NT, SMEM_TOTAL>>>(
        (const float*)d_in[0], (const float*)d_in[1], (const float*)d_in[2],
        (const float*)d_in[3], (const float*)d_in[4], (float*)d_out);
}

// round 8
// speedup vs baseline: 3.3698x; 1.0494x over previous
#include <cuda_runtime.h>
#include <cstdint>

#define NA     17064
#define KTOP   1000
#define NBINS  16384
#define CCAP   4096
#define NT     1024
#define B      16
#define NCTA   128          // 8 CTAs per batch, co-resident (1 CTA/SM)

typedef unsigned long long u64;

// ---------------- static device scratch ----------------
__device__ float    gscore[B][NA];
__device__ unsigned ghist[B][NBINS];      // zero-init; re-zeroed each pass
__device__ unsigned gcidx[B][CCAP];
__device__ unsigned gcnt[B];
__device__ u64      gkey[B][CCAP];
__device__ float    gssc[B][KTOP];
__device__ unsigned gslab[B][KTOP];
__device__ unsigned gvbits[B][32];        // validity bitmask (ballot words)
__device__ float4   gsbox[B][KTOP];
__device__ float    gsx1[B][KTOP], gsy1[B][KTOP], gsx2[B][KTOP],
                    gsy2[B][KTOP], gsar[B][KTOP];
__device__ unsigned gmat[B][KTOP][32];
__device__ unsigned gbarc[B][8];          // per-batch epoch barrier counters

// Exact sigmoid: float exp via double exp (correctly rounded to float =>
// matches faithful libm expf), then float add + div as XLA expands logistic.
__device__ __forceinline__ float sigx(float x) {
    float t = (float)exp(-(double)x);
    return __fdiv_rn(1.0f, __fadd_rn(1.0f, t));
}
// Fast approximate sigmoid — superset selection only.
__device__ __forceinline__ float siga(float x) {
    return __fdividef(1.0f, 1.0f + __expf(-x));
}
// compare-exchange via shfl (bitonic)
__device__ __forceinline__ u64 cex_shfl(u64 v, int j, bool up, int lane) {
    u64 p = __shfl_xor_sync(0xffffffffu, v, j);
    bool lower = ((lane & j) == 0);
    return (lower == up) ? (v > p ? v : p) : (v < p ? v : p);
}
// per-batch barrier (8 CTAs), epoch-based: graph-replay safe, tight spin
__device__ __forceinline__ void bbarrier(int b, int k) {
    __syncthreads();
    if (threadIdx.x == 0) {
        __threadfence();
        unsigned old   = atomicAdd(&gbarc[b][k], 1u);
        unsigned epoch = old >> 3;                 // /8
        volatile unsigned* p = &gbarc[b][k];
        unsigned target = (epoch + 1u) << 3;
        while (*p < target) { }                    // pure spin (1 thread/CTA)
        __threadfence();
    }
    __syncthreads();
}

#define OFF_SDIAG  128000
#define SMEM_TOTAL 132096   // max(32KB sort, 20KB boxes, 125KB mat + 4KB sdiag)

extern __shared__ unsigned char smem_raw[];

__global__ void __launch_bounds__(NT, 1)
fcos_persist(const float* __restrict__ cls, const float* __restrict__ ctr,
             const float* __restrict__ reg, const float* __restrict__ coords,
             const float* __restrict__ pstr, float* __restrict__ out)
{
    const int cta  = blockIdx.x;
    const int b    = cta >> 3;          // batch
    const int r    = cta & 7;           // sub-CTA within batch
    const int tid  = threadIdx.x;
    const int lane = tid & 31;
    const int wid  = tid >> 5;

    __shared__ unsigned chunk[1024];
    __shared__ unsigned super[32];
    __shared__ float redmax[32], redmin[32];
    __shared__ float s_mx, s_mn;
    __shared__ unsigned s_thr, srem[32];

    const float4* clsB = (const float4*)cls + (size_t)b * NA;
    const float*  ctrB = ctr + (size_t)b * NA;

    // ============ Phase 1: approx scores + global histogram (8 CTAs/batch) ==
    if (r == 0 && tid == 0) gcnt[b] = 0;
    for (int i = r * NT + tid; i < NA; i += 8 * NT) {
        float4 c = clsB[i];
        float m = fmaxf(fmaxf(c.x, c.y), fmaxf(c.z, c.w));   // sigmoid monotone
        float score = __fsqrt_rn(siga(m) * siga(ctrB[i]));
        gscore[b][i] = score;
        atomicAdd(&ghist[b][__float_as_uint(score) >> 16], 1u);
    }
    bbarrier(b, 0);

    // ============ Phase 2: threshold (redundant per CTA) + compact ==========
    { unsigned s = 0; int base = tid * 16;
#pragma unroll
      for (int q = 0; q < 16; ++q) s += ghist[b][base + q];
      chunk[tid] = s; }
    __syncthreads();
    { unsigned s = chunk[wid * 32 + lane];
#pragma unroll
      for (int o = 16; o; o >>= 1) s += __shfl_xor_sync(0xffffffffu, s, o);
      if (lane == 0) super[wid] = s; }
    __syncthreads();
    if (tid == 0) {
        unsigned acc = 0; int T = 0;
        for (int sblk = 31; sblk >= 0; --sblk) {
            if (acc + super[sblk] >= KTOP) {
                for (int c = sblk * 32 + 31; c >= sblk * 32; --c) {
                    if (acc + chunk[c] >= KTOP) {
                        for (int bin = c * 16 + 15; bin >= c * 16; --bin) {
                            acc += ghist[b][bin];
                            if (acc >= KTOP) { T = bin; break; }
                        }
                        break;
                    }
                    acc += chunk[c];
                }
                break;
            }
            acc += super[sblk];
        }
        s_thr = (unsigned)(T > 0 ? T - 1 : 0);   // one-bin superset margin
    }
    __syncthreads();
    const unsigned T = s_thr;

    for (int i = r * NT + tid; i < NA; i += 8 * NT) {
        if ((__float_as_uint(gscore[b][i]) >> 16) >= T) {
            unsigned p = atomicAdd(&gcnt[b], 1u);
            if (p < CCAP) gcidx[b][p] = (unsigned)i;
        }
    }
    bbarrier(b, 1);

    // ============ Phase 3: exact rescore (8 CTAs/batch) + ghist re-zero =====
    int C = (int)gcnt[b]; if (C > CCAP) C = CCAP;
    for (int p = r * NT + tid; p < C; p += 8 * NT) {
        unsigned idx = gcidx[b][p];
        float4 c = clsB[idx];
        float xs0 = c.x, xs1 = c.y, xs2 = c.z, xs3 = c.w;
        float m = xs0; int im = 0;
        if (xs1 > m) { m = xs1; im = 1; }
        if (xs2 > m) { m = xs2; im = 2; }
        if (xs3 > m) { m = xs3; im = 3; }
        float sm = sigx(m);                         // == max of the 4 sigmoids
        int lab = im;
        if (im > 0) {                               // tie guard (first-argmax)
            float lim = m - 1e-4f;
            if (xs0 > lim || (im > 1 && xs1 > lim) || (im > 2 && xs2 > lim)) {
                if (xs0 > lim && sigx(xs0) == sm) lab = 0;
                else if (im > 1 && xs1 > lim && sigx(xs1) == sm) lab = 1;
                else if (im > 2 && xs2 > lim && sigx(xs2) == sm) lab = 2;
            }
        }
        float sctr  = sigx(ctrB[idx]);
        float score = __fsqrt_rn(__fmul_rn(sm, sctr));
        gkey[b][p] = ((u64)__float_as_uint(score) << 32)
                   | ((u64)(0x7FFFu - idx) << 4) | (u64)(lab + 1);
    }
    for (int i = r * 2048 + tid; i < (r + 1) * 2048; i += NT)   // re-zero hist
        ghist[b][i] = 0;
    bbarrier(b, 2);

    // ============ Phase 4: sort + box build (1 CTA/batch) ==================
    if (r == 0) {
        u64* cand = (u64*)smem_raw;
        if (C <= 2048) {
            const int base = wid * 64;
            u64 r0 = (base + lane      < C) ? gkey[b][base + lane]      : 0ULL;
            u64 r1 = (base + 32 + lane < C) ? gkey[b][base + 32 + lane] : 0ULL;
#pragma unroll
            for (int k2 = 2; k2 <= 16; k2 <<= 1) {
                bool up = ((lane & k2) == 0);
#pragma unroll
                for (int j = k2 >> 1; j > 0; j >>= 1) {
                    r0 = cex_shfl(r0, j, up, lane);
                    r1 = cex_shfl(r1, j, up, lane);
                }
            }
#pragma unroll
            for (int j = 16; j > 0; j >>= 1) {
                r0 = cex_shfl(r0, j, true,  lane);
                r1 = cex_shfl(r1, j, false, lane);
            }
            {
                bool up = ((base & 64) == 0);
                u64 lo = r0, hi = r1;
                if (up) { r0 = lo > hi ? lo : hi; r1 = lo > hi ? hi : lo; }
                else    { r0 = lo < hi ? lo : hi; r1 = lo < hi ? hi : lo; }
#pragma unroll
                for (int j = 16; j > 0; j >>= 1) {
                    r0 = cex_shfl(r0, j, up, lane);
                    r1 = cex_shfl(r1, j, up, lane);
                }
            }
            for (int k2 = 128; k2 <= 2048; k2 <<= 1) {
                cand[base + lane] = r0; cand[base + 32 + lane] = r1;
                __syncthreads();
                for (int j = k2 >> 1; j >= 64; j >>= 1) {
                    for (int t = tid; t < 2048; t += NT) {
                        int ixj = t ^ j;
                        if (ixj > t) {
                            u64 a = cand[t], b2 = cand[ixj];
                            bool up = ((t & k2) == 0);
                            if (up ? (a < b2) : (a > b2)) { cand[t] = b2; cand[ixj] = a; }
                        }
                    }
                    __syncthreads();
                }
                r0 = cand[base + lane]; r1 = cand[base + 32 + lane];
                bool up = ((base & k2) == 0);
                u64 lo = r0, hi = r1;
                if (up) { r0 = lo > hi ? lo : hi; r1 = lo > hi ? hi : lo; }
                else    { r0 = lo < hi ? lo : hi; r1 = lo < hi ? hi : lo; }
#pragma unroll
                for (int j = 16; j > 0; j >>= 1) {
                    r0 = cex_shfl(r0, j, up, lane);
                    r1 = cex_shfl(r1, j, up, lane);
                }
            }
            cand[base + lane] = r0; cand[base + 32 + lane] = r1;
            __syncthreads();
        } else {
            for (int i = tid; i < CCAP; i += NT)
                cand[i] = (i < C) ? gkey[b][i] : 0ULL;
            __syncthreads();
            for (int k2 = 2; k2 <= CCAP; k2 <<= 1)
                for (int j = k2 >> 1; j > 0; j >>= 1) {
                    for (int t = tid; t < CCAP; t += NT) {
                        int ixj = t ^ j;
                        if (ixj > t) {
                            u64 a = cand[t], b2 = cand[ixj];
                            bool up = ((t & k2) == 0);
                            if (up ? (a < b2) : (a > b2)) { cand[t] = b2; cand[ixj] = a; }
                        }
                    }
                    __syncthreads();
                }
        }

        // gather top-1000, build boxes
        float x1 = 0, y1 = 0, x2 = 0, y2 = 0, score = 0;
        int label = 0; bool validf = false;
        if (tid < KTOP) {
            u64 key = cand[tid];
            score  = __uint_as_float((unsigned)(key >> 32));
            label  = (int)(key & 0xFull);
            int idx = 0x7FFF - (int)((key >> 4) & 0x7FFFull);
            validf = (score >= 0.05f);

            float4 r4 = ((const float4*)reg)[(size_t)b * NA + idx];
            float2 xy = ((const float2*)coords)[idx];
            float  st = pstr[idx];
            x1 = __fsub_rn(xy.x, __fmul_rn(r4.x, st));
            y1 = __fsub_rn(xy.y, __fmul_rn(r4.y, st));
            x2 = __fadd_rn(xy.x, __fmul_rn(r4.z, st));
            y2 = __fadd_rn(xy.y, __fmul_rn(r4.w, st));
            x1 = fminf(fmaxf(x1, 0.0f), 1023.0f);
            y1 = fminf(fmaxf(y1, 0.0f), 799.0f);
            x2 = fminf(fmaxf(x2, 0.0f), 1023.0f);
            y2 = fminf(fmaxf(y2, 0.0f), 799.0f);

            gsbox[b][tid] = make_float4(x1, y1, x2, y2);
            gssc[b][tid]  = score;
            gslab[b][tid] = (unsigned)label;
        }
        // validity bitmask via ballot (warp w covers boxes 32w..32w+31)
        { unsigned vb = __ballot_sync(0xffffffffu, validf);
          if (lane == 0) gvbits[b][wid] = vb; }

        float vmax = -1000000000.0f, vmin = 1000000000.0f;
        if (tid < KTOP && validf) {
            vmax = fmaxf(fmaxf(x1, y1), fmaxf(x2, y2));
            vmin = fminf(fminf(x1, y1), fminf(x2, y2));
        }
#pragma unroll
        for (int o = 16; o; o >>= 1) {
            vmax = fmaxf(vmax, __shfl_xor_sync(0xffffffffu, vmax, o));
            vmin = fminf(vmin, __shfl_xor_sync(0xffffffffu, vmin, o));
        }
        if (lane == 0) { redmax[wid] = vmax; redmin[wid] = vmin; }
        __syncthreads();
        if (tid == 0) {
            float mx = redmax[0], mn = redmin[0];
            for (int w = 1; w < 32; ++w) { mx = fmaxf(mx, redmax[w]); mn = fminf(mn, redmin[w]); }
            s_mx = mx; s_mn = mn;
        }
        __syncthreads();

        if (tid < KTOP) {
            float off = __fmul_rn((float)label, __fadd_rn(__fsub_rn(s_mx, s_mn), 1.0f));
            float a  = __fadd_rn(x1, off), bb = __fadd_rn(y1, off);
            float cc = __fadd_rn(x2, off), dd = __fadd_rn(y2, off);
            gsx1[b][tid] = a;  gsy1[b][tid] = bb;
            gsx2[b][tid] = cc; gsy2[b][tid] = dd;
            gsar[b][tid] = __fmul_rn(__fsub_rn(cc, a), __fsub_rn(dd, bb));
        }
    }
    bbarrier(b, 3);

    // ============ Phase 5: bit-matrix, rows interleaved (8 CTAs/batch) ======
    {
        float* sx1 = (float*)smem_raw;
        float* sy1 = sx1 + KTOP; float* sx2 = sy1 + KTOP;
        float* sy2 = sx2 + KTOP; float* sar = sy2 + KTOP;
        for (int j = tid; j < KTOP; j += NT) {
            sx1[j] = gsx1[b][j]; sy1[j] = gsy1[b][j];
            sx2[j] = gsx2[b][j]; sy2[j] = gsy2[b][j];
            sar[j] = gsar[b][j];
        }
        __syncthreads();

        for (int k = wid; k < 125; k += 32) {
            int i = r + 8 * k;                       // interleaved -> balanced
            float ax1 = sx1[i], ay1 = sy1[i], ax2 = sx2[i], ay2 = sy2[i], aa = sar[i];
            unsigned myword = 0;
            int jc0 = (i + 1) >> 5;
            for (int jc = jc0; jc < 32; ++jc) {      // uniform per warp
                int j = jc * 32 + lane;
                bool sup = false;
                if (j > i && j < KTOP) {
                    float ix1 = fmaxf(ax1, sx1[j]);
                    float iy1 = fmaxf(ay1, sy1[j]);
                    float ix2 = fminf(ax2, sx2[j]);
                    float iy2 = fminf(ay2, sy2[j]);
                    float iw  = fmaxf(__fsub_rn(ix2, ix1), 0.0f);
                    float ih  = fmaxf(__fsub_rn(iy2, iy1), 0.0f);
                    float inter = __fmul_rn(iw, ih);
                    float uni = fmaxf(__fsub_rn(__fadd_rn(aa, sar[j]), inter), 1e-9f);
                    sup = __fdiv_rn(inter, uni) > 0.5f;
                }
                unsigned wbits = __ballot_sync(0xffffffffu, sup);
                if (lane == jc) myword = wbits;
            }
            gmat[b][i][lane] = myword;
        }
    }
    bbarrier(b, 4);

    // ============ Phase 6: block-serial NMS + outputs (1 CTA/batch) =========
    if (r != 0) return;
    {
        unsigned* smat  = (unsigned*)smem_raw;              // [1000][32]
        unsigned* sdiag = (unsigned*)(smem_raw + OFF_SDIAG);// [1024]
        { const uint4* src = (const uint4*)&gmat[b][0][0];
          uint4* dst = (uint4*)smat;
          for (int t = tid; t < KTOP * 8; t += NT) dst[t] = src[t]; }
        for (int i = tid; i < KTOP; i += NT) sdiag[i] = gmat[b][i][i >> 5];
        if (tid >= KTOP) sdiag[tid] = 0u;
        __syncthreads();

        if (wid == 0) {
            unsigned removed = ~gvbits[b][lane];   // lane owns [32*lane, +32)
            for (int bk = 0; bk < 32; ++bk) {
                unsigned curw = __shfl_sync(0xffffffffu, removed, bk);
                unsigned kept = 0;
                if (lane == 0) {
                    const uint4* dg = (const uint4*)(sdiag + bk * 32);
                    unsigned rem = curw;
#pragma unroll
                    for (int q = 0; q < 8; ++q) {
                        uint4 v = dg[q];
                        int j0 = q * 4;
                        if (!((rem >> (j0 + 0)) & 1u)) { kept |= 1u << (j0 + 0); rem |= v.x; }
                        if (!((rem >> (j0 + 1)) & 1u)) { kept |= 1u << (j0 + 1); rem |= v.y; }
                        if (!((rem >> (j0 + 2)) & 1u)) { kept |= 1u << (j0 + 2); rem |= v.z; }
                        if (!((rem >> (j0 + 3)) & 1u)) { kept |= 1u << (j0 + 3); rem |= v.w; }
                    }
                }
                kept = __shfl_sync(0xffffffffu, kept, 0);
#pragma unroll 4
                for (int jj = 0; jj < 32; ++jj) {
                    if ((kept >> jj) & 1u)                 // uniform branch
                        removed |= smat[(bk * 32 + jj) * 32 + lane];
                }
            }
            srem[lane] = removed;
        }
        __syncthreads();

        if (tid < KTOP) {
            bool k = ((srem[tid >> 5] >> (tid & 31)) & 1u) == 0u;
            float so = k ? gssc[b][tid] : 0.0f;
            float lo = k ? (float)gslab[b][tid] : 0.0f;
            float4 bx = gsbox[b][tid];
            if (!k) bx = make_float4(0.f, 0.f, 0.f, 0.f);
            out[(size_t)b * KTOP + tid] = so;
            out[(size_t)(B * KTOP) + (size_t)b * KTOP + tid] = lo;
            size_t base = (size_t)(2 * B * KTOP) + ((size_t)b * KTOP + tid) * 4;
            out[base + 0] = bx.x; out[base + 1] = bx.y;
            out[base + 2] = bx.z; out[base + 3] = bx.w;
        }
    }
}

extern "C" void kernel_launch(void* const* d_in, const int* in_sizes, int n_in,
                              void* d_out, int out_size) {
    (void)in_sizes; (void)n_in; (void)out_size;
    static bool attr_done = false;
    if (!attr_done) {
        cudaFuncSetAttribute(fcos_persist, cudaFuncAttributeMaxDynamicSharedMemorySize,
                             SMEM_TOTAL);
        attr_done = true;
    }
    fcos_persist<<<NCTA, NT, SMEM_TOTAL>>>(
        (const float*)d_in[0], (const float*)d_in[1], (const float*)d_in[2],
        (const float*)d_in[3], (const float*)d_in[4], (float*)d_out);
}